// round 13
// baseline (speedup 1.0000x reference)
#include <cuda_runtime.h>
#include <cuda_fp16.h>
#include <cstdint>

// ---------------- problem constants ----------------
#define BB   2
#define SS   4096
#define DD   2048
#define HH   16
#define HD   128
#define CHUNK 64
#define NC   64
#define MROWS 8192
#define NBH  32
#define QSCALE 0.08838834764831845f
#define WSZ  (DD * DD)

// ---------------- scratch (device globals) ----------------
__device__ __align__(256) __half g_x1[(size_t)MROWS * DD];
__device__ __align__(256) __half g_w1[(size_t)4 * WSZ];
__device__ __align__(256) __half g_q1[(size_t)MROWS * DD];
__device__ __align__(256) __half g_k1[(size_t)MROWS * DD];
__device__ __align__(256) __half g_v1[(size_t)MROWS * DD];
__device__ __align__(256) __half g_o1[(size_t)MROWS * DD];
__device__ __align__(256) __half g_KV[(size_t)NBH * NC * HD * HD];
__device__ __align__(256) __half g_S1[(size_t)NBH * NC * HD * HD];

// ---------------- helpers ----------------
__device__ __forceinline__ uint32_t smem_u32(const void* p) {
    return (uint32_t)__cvta_generic_to_shared(p);
}
__device__ __forceinline__ void cp16(uint32_t d, const void* s) {
    asm volatile("cp.async.cg.shared.global [%0], [%1], 16;\n" :: "r"(d), "l"(s));
}
__device__ __forceinline__ void ldsm4(uint32_t* r, uint32_t a) {
    asm volatile("ldmatrix.sync.aligned.m8n8.x4.shared.b16 {%0,%1,%2,%3}, [%4];\n"
                 : "=r"(r[0]), "=r"(r[1]), "=r"(r[2]), "=r"(r[3]) : "r"(a));
}
__device__ __forceinline__ void ldsm4t(uint32_t* r, uint32_t a) {
    asm volatile("ldmatrix.sync.aligned.m8n8.x4.trans.shared.b16 {%0,%1,%2,%3}, [%4];\n"
                 : "=r"(r[0]), "=r"(r[1]), "=r"(r[2]), "=r"(r[3]) : "r"(a));
}
__device__ __forceinline__ void mma_f16(float* c, const uint32_t* a, const uint32_t* b) {
    asm volatile("mma.sync.aligned.m16n8k16.row.col.f32.f16.f16.f32 "
                 "{%0,%1,%2,%3}, {%4,%5,%6,%7}, {%8,%9}, {%0,%1,%2,%3};\n"
                 : "+f"(c[0]), "+f"(c[1]), "+f"(c[2]), "+f"(c[3])
                 : "r"(a[0]), "r"(a[1]), "r"(a[2]), "r"(a[3]), "r"(b[0]), "r"(b[1]));
}
__device__ __forceinline__ uint32_t pk2h(float a, float b) {
    __half2 t = __floats2half2_rn(a, b);
    return *(uint32_t*)&t;
}
__device__ __forceinline__ void split2h(float a, float b, uint32_t& H, uint32_t& L) {
    float ha = __half2float(__float2half_rn(a));
    float hb = __half2float(__float2half_rn(b));
    H = pk2h(a, b);
    L = pk2h(a - ha, b - hb);
}

// ---------------- fp32 -> fp16 convert (x + 4 weights, one launch) ----------------
// grid (WSZ/1024, 8): y 0..3 -> W matrices, y 4..7 -> quarters of x
__global__ __launch_bounds__(256) void cvt_all(
        const float* __restrict__ x,
        const float* __restrict__ w0, const float* __restrict__ w1f,
        const float* __restrict__ w2f, const float* __restrict__ w3f,
        __half* __restrict__ px, __half* __restrict__ pw) {
    const int y = blockIdx.y;
    size_t i = (size_t)blockIdx.x * 256 + threadIdx.x;
    const float* src;
    uint2* dst;
    if (y < 4) {
        src = (y == 0) ? w0 : (y == 1) ? w1f : (y == 2) ? w2f : w3f;
        dst = (uint2*)(pw + (size_t)y * WSZ);
    } else {
        const size_t qoff = (size_t)(y - 4) * (MROWS * (size_t)DD / 4);
        src = x + qoff;
        dst = (uint2*)(px + qoff);
    }
    float4 v = ((const float4*)src)[i];
    uint2 H;
    H.x = pk2h(v.x, v.y);
    H.y = pk2h(v.z, v.w);
    dst[i] = H;
}

// ================= fp16 single-pass GEMM: C = alpha*A1 B1^T, CTA 128x128, occ 2 =====
// 3-stage cp.async, K-step 64, ONE __syncthreads per iteration.
// Stage 32KB: A1 @0, B1 @16384.
#define KIT 32
#define STG_B 32768
#define GEMM_SMEM (3 * STG_B)   // 98304 -> 2 CTAs per SM

__device__ __forceinline__ void issue_stage(uint32_t sbase,
        const __half* __restrict__ A1, const __half* __restrict__ B1,
        int k0, int tid) {
    #pragma unroll
    for (int i = 0; i < 4; i++) {             // A1: 128 rows x 8 chunks
        int idx = tid + i * 256;              // 0..1023
        int row = idx >> 3, c = idx & 7;
        const __half* src = A1 + (size_t)row * DD + k0 + c * 8;
        cp16(sbase + row * 128 + (((uint32_t)c ^ (row & 7)) << 4), src);
    }
    #pragma unroll
    for (int i = 0; i < 4; i++) {             // B1: 128 rows x 8 chunks
        int idx = tid + i * 256;
        int row = idx >> 3, c = idx & 7;
        const __half* src = B1 + (size_t)row * DD + k0 + c * 8;
        cp16(sbase + 16384 + row * 128 + (((uint32_t)c ^ (row & 7)) << 4), src);
    }
    asm volatile("cp.async.commit_group;\n" ::: "memory");
}

__device__ __forceinline__ void stage_compute(uint32_t sbase, int lane,
                                              int wm0, int wn0, float acc[4][4][4]) {
    const int arow = (lane & 7) + ((lane >> 3) & 1) * 8;
    const int asel = lane >> 4;
    const int brow = (lane & 7) + ((lane >> 4) << 3);
    const int bsel = (lane >> 3) & 1;
    #pragma unroll
    for (int ks = 0; ks < 4; ks++) {
        uint32_t a1[4][4];
        #pragma unroll
        for (int mf = 0; mf < 4; mf++) {
            int row = wm0 + mf * 16 + arow;
            int c = ks * 2 + asel;
            ldsm4(a1[mf], sbase + row * 128 + (((uint32_t)c ^ (row & 7)) << 4));
        }
        uint32_t b1[2][4];
        #pragma unroll
        for (int nq = 0; nq < 2; nq++) {
            int row = wn0 + nq * 16 + brow;
            int c = ks * 2 + bsel;
            ldsm4(b1[nq], sbase + 16384 + row * 128 + (((uint32_t)c ^ (row & 7)) << 4));
        }
        #pragma unroll
        for (int mf = 0; mf < 4; mf++)
            #pragma unroll
            for (int nf = 0; nf < 4; nf++) {
                const uint32_t* b = &b1[nf >> 1][(nf & 1) * 2];
                mma_f16(acc[mf][nf], a1[mf], b);
            }
    }
}

// If Cf != null: fp32 output (grid.x = 16). Else fused QKV (grid.x = 48):
// proj 0 -> Q1*QSCALE ; proj 1 -> K1 ; proj 2 -> V1 (all single fp16 planes).
__global__ __launch_bounds__(256, 2) void gemm_mma(
        const __half* __restrict__ A1, const __half* __restrict__ B1,
        float* __restrict__ Cf,
        uint32_t* __restrict__ Q1, uint32_t* __restrict__ K1,
        uint32_t* __restrict__ V1) {
    extern __shared__ char smc[];
    const uint32_t sb = smem_u32(smc);
    const int tid = threadIdx.x, lane = tid & 31, w = tid >> 5;
    const int bm0 = blockIdx.y * 128;
    const int bnG = blockIdx.x * 128;
    const int wm0 = (w >> 2) * 64, wn0 = (w & 3) * 32;
    const __half* At1 = A1 + (size_t)bm0 * DD;
    const __half* Bt1 = B1 + (size_t)bnG * DD;

    float acc[4][4][4];
    #pragma unroll
    for (int a = 0; a < 4; a++)
        #pragma unroll
        for (int b = 0; b < 4; b++)
            #pragma unroll
            for (int c = 0; c < 4; c++) acc[a][b][c] = 0.f;

    issue_stage(sb + 0 * STG_B, At1, Bt1, 0,  tid);
    issue_stage(sb + 1 * STG_B, At1, Bt1, 64, tid);

    for (int it = 0; it < KIT; ++it) {
        if (it < KIT - 1) asm volatile("cp.async.wait_group 1;\n" ::: "memory");
        else              asm volatile("cp.async.wait_group 0;\n" ::: "memory");
        __syncthreads();
        if (it + 2 < KIT)
            issue_stage(sb + ((it + 2) % 3) * STG_B, At1, Bt1, (it + 2) * 64, tid);
        stage_compute(sb + (it % 3) * STG_B, lane, wm0, wn0, acc);
    }

    const int proj = (Cf == nullptr) ? (bnG >> 11) : 3;
    const int ncol0 = bnG & 2047;
    const float alpha = (proj == 0) ? QSCALE : 1.f;

    const int r0 = lane >> 2, c0 = lane & 3;
    #pragma unroll
    for (int mf = 0; mf < 4; mf++)
        #pragma unroll
        for (int nf = 0; nf < 4; nf++) {
            int row = bm0 + wm0 + mf * 16 + r0;
            int col = ncol0 + wn0 + nf * 8 + c0 * 2;
            float v0 = alpha * acc[mf][nf][0], v1 = alpha * acc[mf][nf][1];
            float v2 = alpha * acc[mf][nf][2], v3 = alpha * acc[mf][nf][3];
            if (Cf) {
                *(float2*)(Cf + (size_t)row * DD + col) = make_float2(v0, v1);
                *(float2*)(Cf + (size_t)(row + 8) * DD + col) = make_float2(v2, v3);
            } else {
                size_t pA = (size_t)row * (DD / 2) + (col >> 1);
                size_t pB = (size_t)(row + 8) * (DD / 2) + (col >> 1);
                uint32_t* Cp = (proj == 0) ? Q1 : (proj == 1) ? K1 : V1;
                Cp[pA] = pk2h(v0, v1);
                Cp[pB] = pk2h(v2, v3);
            }
        }
}

// ================= kv: KV[d][e] = sum_s K[s][d] V[s][e]  (fp16 out) =================
// 4 chunks per CTA, double-buffered cp.async across chunks.
#define KV_CH 4
#define KV_SMEM 65536   // 2 buffers x (k 16KB + v 16KB)
__global__ __launch_bounds__(256, 2) void kv_mma(
        const __half* __restrict__ K1g, const __half* __restrict__ V1g,
        uint32_t* __restrict__ KV) {
    extern __shared__ char smc[];
    const uint32_t sb = smem_u32(smc);
    const int tid = threadIdx.x, lane = tid & 31, w = tid >> 5;
    const int blk = blockIdx.x;                 // 0..511
    const int bh = blk / (NC / KV_CH);
    const int cgrp = blk % (NC / KV_CH);
    const int b = bh / HH, h = bh % HH;

    auto issue_kv = [&](int buf, int ch) {
        size_t grow = (size_t)(b * SS + (cgrp * KV_CH + ch) * CHUNK);
        #pragma unroll
        for (int i = 0; i < 8; i++) {
            int idx = tid + (i & 3) * 256;     // 0..1023
            int t2 = i >> 2;
            int row = idx >> 4, c = idx & 15;
            const __half* src = (t2 ? V1g : K1g) + (grow + row) * DD + h * HD + c * 8;
            cp16(sb + buf * 32768 + t2 * 16384 + row * 256
                 + (((uint32_t)c ^ (row & 7)) << 4), src);
        }
        asm volatile("cp.async.commit_group;\n" ::: "memory");
    };

    issue_kv(0, 0);

    const int md0 = (w >> 1) * 32, ne0 = (w & 1) * 64;
    const int j = lane & 7, g1 = (lane >> 3) & 1, g2 = lane >> 4;
    const int r0 = lane >> 2, c0 = (lane & 3) * 2;

    for (int ch = 0; ch < KV_CH; ch++) {
        if (ch + 1 < KV_CH) {
            issue_kv((ch + 1) & 1, ch + 1);
            asm volatile("cp.async.wait_group 1;\n" ::: "memory");
        } else {
            asm volatile("cp.async.wait_group 0;\n" ::: "memory");
        }
        __syncthreads();

        const uint32_t sbk = sb + (ch & 1) * 32768;
        float acc[2][8][4];
        #pragma unroll
        for (int a = 0; a < 2; a++)
            #pragma unroll
            for (int n = 0; n < 8; n++)
                #pragma unroll
                for (int e = 0; e < 4; e++) acc[a][n][e] = 0.f;

        #pragma unroll
        for (int kb = 0; kb < 4; kb++) {
            uint32_t a1[2][4];
            #pragma unroll
            for (int mf = 0; mf < 2; mf++) {
                int row = kb * 16 + g2 * 8 + j;
                int c = (md0 >> 3) + mf * 2 + g1;
                ldsm4t(a1[mf], sbk + row * 256 + (((uint32_t)c ^ (row & 7)) << 4));
            }
            uint32_t v1[4][4];
            #pragma unroll
            for (int nf2 = 0; nf2 < 4; nf2++) {
                int row = kb * 16 + g1 * 8 + j;
                int c = (ne0 >> 3) + nf2 * 2 + g2;
                ldsm4t(v1[nf2], sbk + 16384 + row * 256 + (((uint32_t)c ^ (row & 7)) << 4));
            }
            #pragma unroll
            for (int mf = 0; mf < 2; mf++)
                #pragma unroll
                for (int nf = 0; nf < 8; nf++) {
                    const uint32_t* bb = &v1[nf >> 1][(nf & 1) * 2];
                    mma_f16(acc[mf][nf], a1[mf], bb);
                }
        }
        uint32_t* out = KV + (size_t)(bh * NC + cgrp * KV_CH + ch) * (HD * HD / 2);
        #pragma unroll
        for (int mf = 0; mf < 2; mf++)
            #pragma unroll
            for (int nf = 0; nf < 8; nf++) {
                int d = md0 + mf * 16 + r0;
                int e = ne0 + nf * 8 + c0;
                out[(size_t)d * (HD / 2) + (e >> 1)] = pk2h(acc[mf][nf][0], acc[mf][nf][1]);
                out[(size_t)(d + 8) * (HD / 2) + (e >> 1)] = pk2h(acc[mf][nf][2], acc[mf][nf][3]);
            }
        __syncthreads();
    }
}

// ================= exclusive chunk scan: fp16 KV -> fp16 S (fp32 accum, uint2) ======
__global__ __launch_bounds__(256) void scan_kernel(const uint2* __restrict__ KV,
                                                   uint2* __restrict__ S1) {
    size_t g = (size_t)blockIdx.x * 256 + threadIdx.x;   // 0 .. NBH*4096-1
    int bh = (int)(g >> 12);
    int p  = (int)(g & 4095);
    const uint2* src = KV + (size_t)bh * NC * 4096 + p;
    uint2* dst = S1 + (size_t)bh * NC * 4096 + p;
    float a0 = 0.f, a1 = 0.f, a2 = 0.f, a3 = 0.f;
    for (int c = 0; c < NC; c++) {
        uint2 tv = src[(size_t)c * 4096];
        float2 t0 = __half22float2(*(__half2*)&tv.x);
        float2 t1 = __half22float2(*(__half2*)&tv.y);
        uint2 ov;
        ov.x = pk2h(a0, a1);
        ov.y = pk2h(a2, a3);
        dst[(size_t)c * 4096] = ov;
        a0 += t0.x; a1 += t0.y; a2 += t1.x; a3 += t1.y;
    }
}

// ================= attn: o = tril(q k^T) v + q S =================
#define ATTN_SMEM 81920
#define AQ1 0
#define AK1 16384
#define AV1 32768
#define AS1 49152

__global__ __launch_bounds__(256, 2) void attn_mma(
        const __half* __restrict__ Q1g, const __half* __restrict__ K1g,
        const __half* __restrict__ V1g, const __half* __restrict__ S1g,
        uint32_t* __restrict__ O1) {
    extern __shared__ char smc[];
    const uint32_t sb = smem_u32(smc);
    const int tid = threadIdx.x, lane = tid & 31, w = tid >> 5;
    const int blk = blockIdx.x;
    const int bh = blk / NC, cch = blk % NC;
    const int b = bh / HH, h = bh % HH;
    const size_t grow = (size_t)(b * SS + cch * CHUNK);

    const __half* tiles[3] = {Q1g, K1g, V1g};
    #pragma unroll
    for (int i = 0; i < 12; i++) {
        int t3 = i >> 2;
        int idx = tid + (i & 3) * 256;      // 0..1023
        int row = idx >> 4, c = idx & 15;
        const __half* src = tiles[t3] + (grow + row) * DD + h * HD + c * 8;
        cp16(sb + t3 * 16384 + row * 256 + (((uint32_t)c ^ (row & 7)) << 4), src);
    }
    const size_t sgb = (size_t)blk * (HD * HD);
    #pragma unroll
    for (int i = 0; i < 8; i++) {
        int idx = tid + i * 256;            // 0..2047
        int row = idx >> 4, c = idx & 15;
        const __half* src = S1g + sgb + (size_t)row * HD + c * 8;
        cp16(sb + AS1 + row * 256 + (((uint32_t)c ^ (row & 7)) << 4), src);
    }
    asm volatile("cp.async.commit_group;\ncp.async.wait_group 0;\n" ::: "memory");
    __syncthreads();

    const int mrow = (w >> 1) * 16, nh = w & 1;
    const int arow = (lane & 7) + ((lane >> 3) & 1) * 8;
    const int asel = lane >> 4;
    const int brow = (lane & 7) + ((lane >> 4) << 3);
    const int bsel = (lane >> 3) & 1;
    const int j = lane & 7, g1 = (lane >> 3) & 1, g2 = lane >> 4;

    // ---- qk^T ----
    float qk[8][4];
    #pragma unroll
    for (int n = 0; n < 8; n++)
        #pragma unroll
        for (int e = 0; e < 4; e++) qk[n][e] = 0.f;

    #pragma unroll
    for (int kb = 0; kb < 8; kb++) {
        uint32_t q1[4];
        {
            int row = mrow + arow;
            int c = kb * 2 + asel;
            ldsm4(q1, sb + AQ1 + row * 256 + (((uint32_t)c ^ (row & 7)) << 4));
        }
        uint32_t k1[4][4];
        #pragma unroll
        for (int nq = 0; nq < 4; nq++) {
            int row = nq * 16 + brow;
            int c = kb * 2 + bsel;
            ldsm4(k1[nq], sb + AK1 + row * 256 + (((uint32_t)c ^ (row & 7)) << 4));
        }
        #pragma unroll
        for (int nf = 0; nf < 8; nf++) {
            const uint32_t* bb = &k1[nf >> 1][(nf & 1) * 2];
            mma_f16(qk[nf], q1, bb);
        }
    }
    // ---- causal mask ----
    const int r0 = lane >> 2, c0 = (lane & 3) * 2;
    #pragma unroll
    for (int nf = 0; nf < 8; nf++)
        #pragma unroll
        for (int e = 0; e < 4; e++) {
            int rloc = mrow + r0 + ((e >= 2) ? 8 : 0);
            int scol = nf * 8 + c0 + (e & 1);
            if (scol > rloc) qk[nf][e] = 0.f;
        }

    float o[8][4];
    #pragma unroll
    for (int n = 0; n < 8; n++)
        #pragma unroll
        for (int e = 0; e < 4; e++) o[n][e] = 0.f;

    // ---- intra: o += attn @ V  (2-pass register split of attn) ----
    #pragma unroll
    for (int kb2 = 0; kb2 < 4; kb2++) {
        uint32_t Ah[4], Al[4];
        split2h(qk[2 * kb2][0],     qk[2 * kb2][1],     Ah[0], Al[0]);
        split2h(qk[2 * kb2][2],     qk[2 * kb2][3],     Ah[1], Al[1]);
        split2h(qk[2 * kb2 + 1][0], qk[2 * kb2 + 1][1], Ah[2], Al[2]);
        split2h(qk[2 * kb2 + 1][2], qk[2 * kb2 + 1][3], Ah[3], Al[3]);
        uint32_t v1[4][4];
        #pragma unroll
        for (int nf2 = 0; nf2 < 4; nf2++) {
            int row = kb2 * 16 + g1 * 8 + j;
            int c = nh * 8 + nf2 * 2 + g2;
            ldsm4t(v1[nf2], sb + AV1 + row * 256 + (((uint32_t)c ^ (row & 7)) << 4));
        }
        #pragma unroll
        for (int nf = 0; nf < 8; nf++) {
            const uint32_t* bb = &v1[nf >> 1][(nf & 1) * 2];
            mma_f16(o[nf], Ah, bb);
            mma_f16(o[nf], Al, bb);
        }
    }
    // ---- inter: o += q @ S ----
    #pragma unroll
    for (int kb = 0; kb < 8; kb++) {
        uint32_t q1[4];
        {
            int row = mrow + arow;
            int c = kb * 2 + asel;
            ldsm4(q1, sb + AQ1 + row * 256 + (((uint32_t)c ^ (row & 7)) << 4));
        }
        uint32_t s1[4][4];
        #pragma unroll
        for (int nf2 = 0; nf2 < 4; nf2++) {
            int row = kb * 16 + g1 * 8 + j;
            int c = nh * 8 + nf2 * 2 + g2;
            ldsm4t(s1[nf2], sb + AS1 + row * 256 + (((uint32_t)c ^ (row & 7)) << 4));
        }
        #pragma unroll
        for (int nf = 0; nf < 8; nf++) {
            const uint32_t* bb = &s1[nf >> 1][(nf & 1) * 2];
            mma_f16(o[nf], q1, bb);
        }
    }
    // ---- epilogue: write o as single fp16 plane ----
    #pragma unroll
    for (int nf = 0; nf < 8; nf++) {
        int col = h * HD + nh * 64 + nf * 8 + c0;
        size_t pA = (grow + mrow + r0) * (DD / 2) + (col >> 1);
        size_t pB = (grow + mrow + r0 + 8) * (DD / 2) + (col >> 1);
        O1[pA] = pk2h(o[nf][0], o[nf][1]);
        O1[pB] = pk2h(o[nf][2], o[nf][3]);
    }
}

// ---------------------------------------------------------------------------
extern "C" void kernel_launch(void* const* d_in, const int* in_sizes, int n_in,
                              void* d_out, int out_size) {
    const float* x  = (const float*)d_in[0];
    const float* Wq = (const float*)d_in[1];
    const float* Wk = (const float*)d_in[2];
    const float* Wv = (const float*)d_in[3];
    const float* Wo = (const float*)d_in[4];
    float* out = (float*)d_out;

    __half *px1, *pw1, *pq1, *pk1, *pv1, *po1, *pS1, *pKV;
    cudaGetSymbolAddress((void**)&px1, g_x1);
    cudaGetSymbolAddress((void**)&pw1, g_w1);
    cudaGetSymbolAddress((void**)&pq1, g_q1);
    cudaGetSymbolAddress((void**)&pk1, g_k1);
    cudaGetSymbolAddress((void**)&pv1, g_v1);
    cudaGetSymbolAddress((void**)&po1, g_o1);
    cudaGetSymbolAddress((void**)&pS1, g_S1);
    cudaGetSymbolAddress((void**)&pKV, g_KV);

    cudaFuncSetAttribute(gemm_mma, cudaFuncAttributeMaxDynamicSharedMemorySize, GEMM_SMEM);
    cudaFuncSetAttribute(kv_mma,   cudaFuncAttributeMaxDynamicSharedMemorySize, KV_SMEM);
    cudaFuncSetAttribute(attn_mma, cudaFuncAttributeMaxDynamicSharedMemorySize, ATTN_SMEM);

    // converts: x and all W -> single fp16 planes, one launch
    dim3 cgrid(WSZ / 1024, 8);
    cvt_all<<<cgrid, 256>>>(x, Wq, Wk, Wv, Wo, px1, pw1);

    // fused Q,K,V projections (B = [Wq; Wk; Wv] contiguous in g_w1)
    dim3 qkvgrid(3 * DD / 128, MROWS / 128);   // (48, 64)
    gemm_mma<<<qkvgrid, 256, GEMM_SMEM>>>(px1, pw1, nullptr,
                                          (uint32_t*)pq1, (uint32_t*)pk1,
                                          (uint32_t*)pv1);

    kv_mma<<<NBH * NC / KV_CH, 256, KV_SMEM>>>(pk1, pv1, (uint32_t*)pKV);
    scan_kernel<<<(NBH * 4096) / 256, 256>>>((const uint2*)pKV, (uint2*)pS1);
    attn_mma<<<NBH * NC, 256, ATTN_SMEM>>>(pq1, pk1, pv1, pS1, (uint32_t*)po1);

    // output projection (fp32 out)
    dim3 ogrid(DD / 128, MROWS / 128);         // (16, 64)
    gemm_mma<<<ogrid, 256, GEMM_SMEM>>>(po1, pw1 + 3 * (size_t)WSZ, out,
                                        nullptr, nullptr, nullptr);

    (void)in_sizes; (void)n_in; (void)out_size;
}

// round 14
// speedup vs baseline: 1.0287x; 1.0287x over previous
#include <cuda_runtime.h>
#include <cuda_fp16.h>
#include <cstdint>

// ---------------- problem constants ----------------
#define BB   2
#define SS   4096
#define DD   2048
#define HH   16
#define HD   128
#define CHUNK 64
#define NC   64
#define MROWS 8192
#define NBH  32
#define QSCALE 0.08838834764831845f
#define WSZ  (DD * DD)

// ---------------- scratch (device globals) ----------------
__device__ __align__(256) __half g_x1[(size_t)MROWS * DD];
__device__ __align__(256) __half g_w1[(size_t)4 * WSZ];
__device__ __align__(256) __half g_q1[(size_t)MROWS * DD];
__device__ __align__(256) __half g_k1[(size_t)MROWS * DD];
__device__ __align__(256) __half g_v1[(size_t)MROWS * DD];
__device__ __align__(256) __half g_o1[(size_t)MROWS * DD];
__device__ __align__(256) __half g_KV[(size_t)NBH * NC * HD * HD];
__device__ __align__(256) __half g_S1[(size_t)NBH * NC * HD * HD];

// ---------------- helpers ----------------
__device__ __forceinline__ uint32_t smem_u32(const void* p) {
    return (uint32_t)__cvta_generic_to_shared(p);
}
__device__ __forceinline__ void cp16(uint32_t d, const void* s) {
    asm volatile("cp.async.cg.shared.global [%0], [%1], 16;\n" :: "r"(d), "l"(s));
}
__device__ __forceinline__ void ldsm4(uint32_t* r, uint32_t a) {
    asm volatile("ldmatrix.sync.aligned.m8n8.x4.shared.b16 {%0,%1,%2,%3}, [%4];\n"
                 : "=r"(r[0]), "=r"(r[1]), "=r"(r[2]), "=r"(r[3]) : "r"(a));
}
__device__ __forceinline__ void ldsm4t(uint32_t* r, uint32_t a) {
    asm volatile("ldmatrix.sync.aligned.m8n8.x4.trans.shared.b16 {%0,%1,%2,%3}, [%4];\n"
                 : "=r"(r[0]), "=r"(r[1]), "=r"(r[2]), "=r"(r[3]) : "r"(a));
}
__device__ __forceinline__ void mma_f16(float* c, const uint32_t* a, const uint32_t* b) {
    asm volatile("mma.sync.aligned.m16n8k16.row.col.f32.f16.f16.f32 "
                 "{%0,%1,%2,%3}, {%4,%5,%6,%7}, {%8,%9}, {%0,%1,%2,%3};\n"
                 : "+f"(c[0]), "+f"(c[1]), "+f"(c[2]), "+f"(c[3])
                 : "r"(a[0]), "r"(a[1]), "r"(a[2]), "r"(a[3]), "r"(b[0]), "r"(b[1]));
}
__device__ __forceinline__ uint32_t pk2h(float a, float b) {
    __half2 t = __floats2half2_rn(a, b);
    return *(uint32_t*)&t;
}
__device__ __forceinline__ void split2h(float a, float b, uint32_t& H, uint32_t& L) {
    float ha = __half2float(__float2half_rn(a));
    float hb = __half2float(__float2half_rn(b));
    H = pk2h(a, b);
    L = pk2h(a - ha, b - hb);
}

// ---------------- fp32 -> fp16 convert (x + 4 weights, one launch) ----------------
// grid (WSZ/1024, 8): y 0..3 -> W matrices, y 4..7 -> quarters of x
__global__ __launch_bounds__(256) void cvt_all(
        const float* __restrict__ x,
        const float* __restrict__ w0, const float* __restrict__ w1f,
        const float* __restrict__ w2f, const float* __restrict__ w3f,
        __half* __restrict__ px, __half* __restrict__ pw) {
    const int y = blockIdx.y;
    size_t i = (size_t)blockIdx.x * 256 + threadIdx.x;
    const float* src;
    uint2* dst;
    if (y < 4) {
        src = (y == 0) ? w0 : (y == 1) ? w1f : (y == 2) ? w2f : w3f;
        dst = (uint2*)(pw + (size_t)y * WSZ);
    } else {
        const size_t qoff = (size_t)(y - 4) * (MROWS * (size_t)DD / 4);
        src = x + qoff;
        dst = (uint2*)(px + qoff);
    }
    float4 v = ((const float4*)src)[i];
    uint2 H;
    H.x = pk2h(v.x, v.y);
    H.y = pk2h(v.z, v.w);
    dst[i] = H;
}

// ================= fp16 single-pass GEMM: C = alpha*A1 B1^T, CTA 128x128, occ 2 =====
// R12-proven loop: 2-stage cp.async, K-step 64, issue->wait->sync->compute->sync.
// Stage 32KB: A1 @0, B1 @16384.
#define KIT 32
#define STG_B 32768
#define GEMM_SMEM (2 * STG_B)   // 65536 -> 2 CTAs per SM

__device__ __forceinline__ void issue_stage(uint32_t sbase,
        const __half* __restrict__ A1, const __half* __restrict__ B1,
        int k0, int tid) {
    #pragma unroll
    for (int i = 0; i < 4; i++) {             // A1: 128 rows x 8 chunks
        int idx = tid + i * 256;              // 0..1023
        int row = idx >> 3, c = idx & 7;
        const __half* src = A1 + (size_t)row * DD + k0 + c * 8;
        cp16(sbase + row * 128 + (((uint32_t)c ^ (row & 7)) << 4), src);
    }
    #pragma unroll
    for (int i = 0; i < 4; i++) {             // B1: 128 rows x 8 chunks
        int idx = tid + i * 256;
        int row = idx >> 3, c = idx & 7;
        const __half* src = B1 + (size_t)row * DD + k0 + c * 8;
        cp16(sbase + 16384 + row * 128 + (((uint32_t)c ^ (row & 7)) << 4), src);
    }
    asm volatile("cp.async.commit_group;\n" ::: "memory");
}

__device__ __forceinline__ void stage_compute(uint32_t sbase, int lane,
                                              int wm0, int wn0, float acc[4][4][4]) {
    const int arow = (lane & 7) + ((lane >> 3) & 1) * 8;
    const int asel = lane >> 4;
    const int brow = (lane & 7) + ((lane >> 4) << 3);
    const int bsel = (lane >> 3) & 1;
    #pragma unroll
    for (int ks = 0; ks < 4; ks++) {
        uint32_t a1[4][4];
        #pragma unroll
        for (int mf = 0; mf < 4; mf++) {
            int row = wm0 + mf * 16 + arow;
            int c = ks * 2 + asel;
            ldsm4(a1[mf], sbase + row * 128 + (((uint32_t)c ^ (row & 7)) << 4));
        }
        uint32_t b1[2][4];
        #pragma unroll
        for (int nq = 0; nq < 2; nq++) {
            int row = wn0 + nq * 16 + brow;
            int c = ks * 2 + bsel;
            ldsm4(b1[nq], sbase + 16384 + row * 128 + (((uint32_t)c ^ (row & 7)) << 4));
        }
        #pragma unroll
        for (int mf = 0; mf < 4; mf++)
            #pragma unroll
            for (int nf = 0; nf < 4; nf++) {
                const uint32_t* b = &b1[nf >> 1][(nf & 1) * 2];
                mma_f16(acc[mf][nf], a1[mf], b);
            }
    }
}

// If Cf != null: fp32 output (grid.x = 16). Else fused QKV (grid.x = 48):
// proj 0 -> Q1*QSCALE ; proj 1 -> K1 ; proj 2 -> V1 (all single fp16 planes).
__global__ __launch_bounds__(256, 2) void gemm_mma(
        const __half* __restrict__ A1, const __half* __restrict__ B1,
        float* __restrict__ Cf,
        uint32_t* __restrict__ Q1, uint32_t* __restrict__ K1,
        uint32_t* __restrict__ V1) {
    extern __shared__ char smc[];
    const uint32_t sb = smem_u32(smc);
    const int tid = threadIdx.x, lane = tid & 31, w = tid >> 5;
    const int bm0 = blockIdx.y * 128;
    const int bnG = blockIdx.x * 128;
    const int wm0 = (w >> 2) * 64, wn0 = (w & 3) * 32;
    const __half* At1 = A1 + (size_t)bm0 * DD;
    const __half* Bt1 = B1 + (size_t)bnG * DD;

    float acc[4][4][4];
    #pragma unroll
    for (int a = 0; a < 4; a++)
        #pragma unroll
        for (int b = 0; b < 4; b++)
            #pragma unroll
            for (int c = 0; c < 4; c++) acc[a][b][c] = 0.f;

    issue_stage(sb, At1, Bt1, 0, tid);

    for (int it = 0; it < KIT; ++it) {
        if (it + 1 < KIT) {
            issue_stage(sb + ((it + 1) & 1) * STG_B, At1, Bt1, (it + 1) * 64, tid);
            asm volatile("cp.async.wait_group 1;\n" ::: "memory");
        } else {
            asm volatile("cp.async.wait_group 0;\n" ::: "memory");
        }
        __syncthreads();
        stage_compute(sb + (it & 1) * STG_B, lane, wm0, wn0, acc);
        __syncthreads();
    }

    const int proj = (Cf == nullptr) ? (bnG >> 11) : 3;
    const int ncol0 = bnG & 2047;
    const float alpha = (proj == 0) ? QSCALE : 1.f;

    const int r0 = lane >> 2, c0 = lane & 3;
    #pragma unroll
    for (int mf = 0; mf < 4; mf++)
        #pragma unroll
        for (int nf = 0; nf < 4; nf++) {
            int row = bm0 + wm0 + mf * 16 + r0;
            int col = ncol0 + wn0 + nf * 8 + c0 * 2;
            float v0 = alpha * acc[mf][nf][0], v1 = alpha * acc[mf][nf][1];
            float v2 = alpha * acc[mf][nf][2], v3 = alpha * acc[mf][nf][3];
            if (Cf) {
                *(float2*)(Cf + (size_t)row * DD + col) = make_float2(v0, v1);
                *(float2*)(Cf + (size_t)(row + 8) * DD + col) = make_float2(v2, v3);
            } else {
                size_t pA = (size_t)row * (DD / 2) + (col >> 1);
                size_t pB = (size_t)(row + 8) * (DD / 2) + (col >> 1);
                uint32_t* Cp = (proj == 0) ? Q1 : (proj == 1) ? K1 : V1;
                Cp[pA] = pk2h(v0, v1);
                Cp[pB] = pk2h(v2, v3);
            }
        }
}

// ================= kv: KV[d][e] = sum_s K[s][d] V[s][e]  (fp16 out) =================
// 4 chunks per CTA, double-buffered cp.async across chunks.
#define KV_CH 4
#define KV_SMEM 65536   // 2 buffers x (k 16KB + v 16KB)
__global__ __launch_bounds__(256, 2) void kv_mma(
        const __half* __restrict__ K1g, const __half* __restrict__ V1g,
        uint32_t* __restrict__ KV) {
    extern __shared__ char smc[];
    const uint32_t sb = smem_u32(smc);
    const int tid = threadIdx.x, lane = tid & 31, w = tid >> 5;
    const int blk = blockIdx.x;                 // 0..511
    const int bh = blk / (NC / KV_CH);
    const int cgrp = blk % (NC / KV_CH);
    const int b = bh / HH, h = bh % HH;

    auto issue_kv = [&](int buf, int ch) {
        size_t grow = (size_t)(b * SS + (cgrp * KV_CH + ch) * CHUNK);
        #pragma unroll
        for (int i = 0; i < 8; i++) {
            int idx = tid + (i & 3) * 256;     // 0..1023
            int t2 = i >> 2;
            int row = idx >> 4, c = idx & 15;
            const __half* src = (t2 ? V1g : K1g) + (grow + row) * DD + h * HD + c * 8;
            cp16(sb + buf * 32768 + t2 * 16384 + row * 256
                 + (((uint32_t)c ^ (row & 7)) << 4), src);
        }
        asm volatile("cp.async.commit_group;\n" ::: "memory");
    };

    issue_kv(0, 0);

    const int md0 = (w >> 1) * 32, ne0 = (w & 1) * 64;
    const int j = lane & 7, g1 = (lane >> 3) & 1, g2 = lane >> 4;
    const int r0 = lane >> 2, c0 = (lane & 3) * 2;

    for (int ch = 0; ch < KV_CH; ch++) {
        if (ch + 1 < KV_CH) {
            issue_kv((ch + 1) & 1, ch + 1);
            asm volatile("cp.async.wait_group 1;\n" ::: "memory");
        } else {
            asm volatile("cp.async.wait_group 0;\n" ::: "memory");
        }
        __syncthreads();

        const uint32_t sbk = sb + (ch & 1) * 32768;
        float acc[2][8][4];
        #pragma unroll
        for (int a = 0; a < 2; a++)
            #pragma unroll
            for (int n = 0; n < 8; n++)
                #pragma unroll
                for (int e = 0; e < 4; e++) acc[a][n][e] = 0.f;

        #pragma unroll
        for (int kb = 0; kb < 4; kb++) {
            uint32_t a1[2][4];
            #pragma unroll
            for (int mf = 0; mf < 2; mf++) {
                int row = kb * 16 + g2 * 8 + j;
                int c = (md0 >> 3) + mf * 2 + g1;
                ldsm4t(a1[mf], sbk + row * 256 + (((uint32_t)c ^ (row & 7)) << 4));
            }
            uint32_t v1[4][4];
            #pragma unroll
            for (int nf2 = 0; nf2 < 4; nf2++) {
                int row = kb * 16 + g1 * 8 + j;
                int c = (ne0 >> 3) + nf2 * 2 + g2;
                ldsm4t(v1[nf2], sbk + 16384 + row * 256 + (((uint32_t)c ^ (row & 7)) << 4));
            }
            #pragma unroll
            for (int mf = 0; mf < 2; mf++)
                #pragma unroll
                for (int nf = 0; nf < 8; nf++) {
                    const uint32_t* bb = &v1[nf >> 1][(nf & 1) * 2];
                    mma_f16(acc[mf][nf], a1[mf], bb);
                }
        }
        uint32_t* out = KV + (size_t)(bh * NC + cgrp * KV_CH + ch) * (HD * HD / 2);
        #pragma unroll
        for (int mf = 0; mf < 2; mf++)
            #pragma unroll
            for (int nf = 0; nf < 8; nf++) {
                int d = md0 + mf * 16 + r0;
                int e = ne0 + nf * 8 + c0;
                out[(size_t)d * (HD / 2) + (e >> 1)] = pk2h(acc[mf][nf][0], acc[mf][nf][1]);
                out[(size_t)(d + 8) * (HD / 2) + (e >> 1)] = pk2h(acc[mf][nf][2], acc[mf][nf][3]);
            }
        __syncthreads();
    }
}

// ================= exclusive chunk scan: fp16 KV -> fp16 S (fp32 accum, uint2) ======
__global__ __launch_bounds__(256) void scan_kernel(const uint2* __restrict__ KV,
                                                   uint2* __restrict__ S1) {
    size_t g = (size_t)blockIdx.x * 256 + threadIdx.x;   // 0 .. NBH*4096-1
    int bh = (int)(g >> 12);
    int p  = (int)(g & 4095);
    const uint2* src = KV + (size_t)bh * NC * 4096 + p;
    uint2* dst = S1 + (size_t)bh * NC * 4096 + p;
    float a0 = 0.f, a1 = 0.f, a2 = 0.f, a3 = 0.f;
    for (int c = 0; c < NC; c++) {
        uint2 tv = src[(size_t)c * 4096];
        float2 t0 = __half22float2(*(__half2*)&tv.x);
        float2 t1 = __half22float2(*(__half2*)&tv.y);
        uint2 ov;
        ov.x = pk2h(a0, a1);
        ov.y = pk2h(a2, a3);
        dst[(size_t)c * 4096] = ov;
        a0 += t0.x; a1 += t0.y; a2 += t1.x; a3 += t1.y;
    }
}

// ================= attn: o = tril(q k^T) v + q S =================
#define ATTN_SMEM 81920
#define AQ1 0
#define AK1 16384
#define AV1 32768
#define AS1 49152

__global__ __launch_bounds__(256, 2) void attn_mma(
        const __half* __restrict__ Q1g, const __half* __restrict__ K1g,
        const __half* __restrict__ V1g, const __half* __restrict__ S1g,
        uint32_t* __restrict__ O1) {
    extern __shared__ char smc[];
    const uint32_t sb = smem_u32(smc);
    const int tid = threadIdx.x, lane = tid & 31, w = tid >> 5;
    const int blk = blockIdx.x;
    const int bh = blk / NC, cch = blk % NC;
    const int b = bh / HH, h = bh % HH;
    const size_t grow = (size_t)(b * SS + cch * CHUNK);

    const __half* tiles[3] = {Q1g, K1g, V1g};
    #pragma unroll
    for (int i = 0; i < 12; i++) {
        int t3 = i >> 2;
        int idx = tid + (i & 3) * 256;      // 0..1023
        int row = idx >> 4, c = idx & 15;
        const __half* src = tiles[t3] + (grow + row) * DD + h * HD + c * 8;
        cp16(sb + t3 * 16384 + row * 256 + (((uint32_t)c ^ (row & 7)) << 4), src);
    }
    const size_t sgb = (size_t)blk * (HD * HD);
    #pragma unroll
    for (int i = 0; i < 8; i++) {
        int idx = tid + i * 256;            // 0..2047
        int row = idx >> 4, c = idx & 15;
        const __half* src = S1g + sgb + (size_t)row * HD + c * 8;
        cp16(sb + AS1 + row * 256 + (((uint32_t)c ^ (row & 7)) << 4), src);
    }
    asm volatile("cp.async.commit_group;\ncp.async.wait_group 0;\n" ::: "memory");
    __syncthreads();

    const int mrow = (w >> 1) * 16, nh = w & 1;
    const int arow = (lane & 7) + ((lane >> 3) & 1) * 8;
    const int asel = lane >> 4;
    const int brow = (lane & 7) + ((lane >> 4) << 3);
    const int bsel = (lane >> 3) & 1;
    const int j = lane & 7, g1 = (lane >> 3) & 1, g2 = lane >> 4;

    // ---- qk^T ----
    float qk[8][4];
    #pragma unroll
    for (int n = 0; n < 8; n++)
        #pragma unroll
        for (int e = 0; e < 4; e++) qk[n][e] = 0.f;

    #pragma unroll
    for (int kb = 0; kb < 8; kb++) {
        uint32_t q1[4];
        {
            int row = mrow + arow;
            int c = kb * 2 + asel;
            ldsm4(q1, sb + AQ1 + row * 256 + (((uint32_t)c ^ (row & 7)) << 4));
        }
        uint32_t k1[4][4];
        #pragma unroll
        for (int nq = 0; nq < 4; nq++) {
            int row = nq * 16 + brow;
            int c = kb * 2 + bsel;
            ldsm4(k1[nq], sb + AK1 + row * 256 + (((uint32_t)c ^ (row & 7)) << 4));
        }
        #pragma unroll
        for (int nf = 0; nf < 8; nf++) {
            const uint32_t* bb = &k1[nf >> 1][(nf & 1) * 2];
            mma_f16(qk[nf], q1, bb);
        }
    }
    // ---- causal mask ----
    const int r0 = lane >> 2, c0 = (lane & 3) * 2;
    #pragma unroll
    for (int nf = 0; nf < 8; nf++)
        #pragma unroll
        for (int e = 0; e < 4; e++) {
            int rloc = mrow + r0 + ((e >= 2) ? 8 : 0);
            int scol = nf * 8 + c0 + (e & 1);
            if (scol > rloc) qk[nf][e] = 0.f;
        }

    float o[8][4];
    #pragma unroll
    for (int n = 0; n < 8; n++)
        #pragma unroll
        for (int e = 0; e < 4; e++) o[n][e] = 0.f;

    // ---- intra: o += attn @ V  (2-pass register split of attn) ----
    #pragma unroll
    for (int kb2 = 0; kb2 < 4; kb2++) {
        uint32_t Ah[4], Al[4];
        split2h(qk[2 * kb2][0],     qk[2 * kb2][1],     Ah[0], Al[0]);
        split2h(qk[2 * kb2][2],     qk[2 * kb2][3],     Ah[1], Al[1]);
        split2h(qk[2 * kb2 + 1][0], qk[2 * kb2 + 1][1], Ah[2], Al[2]);
        split2h(qk[2 * kb2 + 1][2], qk[2 * kb2 + 1][3], Ah[3], Al[3]);
        uint32_t v1[4][4];
        #pragma unroll
        for (int nf2 = 0; nf2 < 4; nf2++) {
            int row = kb2 * 16 + g1 * 8 + j;
            int c = nh * 8 + nf2 * 2 + g2;
            ldsm4t(v1[nf2], sb + AV1 + row * 256 + (((uint32_t)c ^ (row & 7)) << 4));
        }
        #pragma unroll
        for (int nf = 0; nf < 8; nf++) {
            const uint32_t* bb = &v1[nf >> 1][(nf & 1) * 2];
            mma_f16(o[nf], Ah, bb);
            mma_f16(o[nf], Al, bb);
        }
    }
    // ---- inter: o += q @ S ----
    #pragma unroll
    for (int kb = 0; kb < 8; kb++) {
        uint32_t q1[4];
        {
            int row = mrow + arow;
            int c = kb * 2 + asel;
            ldsm4(q1, sb + AQ1 + row * 256 + (((uint32_t)c ^ (row & 7)) << 4));
        }
        uint32_t s1[4][4];
        #pragma unroll
        for (int nf2 = 0; nf2 < 4; nf2++) {
            int row = kb * 16 + g1 * 8 + j;
            int c = nh * 8 + nf2 * 2 + g2;
            ldsm4t(s1[nf2], sb + AS1 + row * 256 + (((uint32_t)c ^ (row & 7)) << 4));
        }
        #pragma unroll
        for (int nf = 0; nf < 8; nf++) {
            const uint32_t* bb = &s1[nf >> 1][(nf & 1) * 2];
            mma_f16(o[nf], q1, bb);
        }
    }
    // ---- epilogue: write o as single fp16 plane ----
    #pragma unroll
    for (int nf = 0; nf < 8; nf++) {
        int col = h * HD + nh * 64 + nf * 8 + c0;
        size_t pA = (grow + mrow + r0) * (DD / 2) + (col >> 1);
        size_t pB = (grow + mrow + r0 + 8) * (DD / 2) + (col >> 1);
        O1[pA] = pk2h(o[nf][0], o[nf][1]);
        O1[pB] = pk2h(o[nf][2], o[nf][3]);
    }
}

// ---------------------------------------------------------------------------
extern "C" void kernel_launch(void* const* d_in, const int* in_sizes, int n_in,
                              void* d_out, int out_size) {
    const float* x  = (const float*)d_in[0];
    const float* Wq = (const float*)d_in[1];
    const float* Wk = (const float*)d_in[2];
    const float* Wv = (const float*)d_in[3];
    const float* Wo = (const float*)d_in[4];
    float* out = (float*)d_out;

    __half *px1, *pw1, *pq1, *pk1, *pv1, *po1, *pS1, *pKV;
    cudaGetSymbolAddress((void**)&px1, g_x1);
    cudaGetSymbolAddress((void**)&pw1, g_w1);
    cudaGetSymbolAddress((void**)&pq1, g_q1);
    cudaGetSymbolAddress((void**)&pk1, g_k1);
    cudaGetSymbolAddress((void**)&pv1, g_v1);
    cudaGetSymbolAddress((void**)&po1, g_o1);
    cudaGetSymbolAddress((void**)&pS1, g_S1);
    cudaGetSymbolAddress((void**)&pKV, g_KV);

    cudaFuncSetAttribute(gemm_mma, cudaFuncAttributeMaxDynamicSharedMemorySize, GEMM_SMEM);
    cudaFuncSetAttribute(kv_mma,   cudaFuncAttributeMaxDynamicSharedMemorySize, KV_SMEM);
    cudaFuncSetAttribute(attn_mma, cudaFuncAttributeMaxDynamicSharedMemorySize, ATTN_SMEM);

    // converts: x and all W -> single fp16 planes, one launch
    dim3 cgrid(WSZ / 1024, 8);
    cvt_all<<<cgrid, 256>>>(x, Wq, Wk, Wv, Wo, px1, pw1);

    // fused Q,K,V projections (B = [Wq; Wk; Wv] contiguous in g_w1)
    dim3 qkvgrid(3 * DD / 128, MROWS / 128);   // (48, 64)
    gemm_mma<<<qkvgrid, 256, GEMM_SMEM>>>(px1, pw1, nullptr,
                                          (uint32_t*)pq1, (uint32_t*)pk1,
                                          (uint32_t*)pv1);

    kv_mma<<<NBH * NC / KV_CH, 256, KV_SMEM>>>(pk1, pv1, (uint32_t*)pKV);
    scan_kernel<<<(NBH * 4096) / 256, 256>>>((const uint2*)pKV, (uint2*)pS1);
    attn_mma<<<NBH * NC, 256, ATTN_SMEM>>>(pq1, pk1, pv1, pS1, (uint32_t*)po1);

    // output projection (fp32 out)
    dim3 ogrid(DD / 128, MROWS / 128);         // (16, 64)
    gemm_mma<<<ogrid, 256, GEMM_SMEM>>>(po1, pw1 + 3 * (size_t)WSZ, out,
                                        nullptr, nullptr, nullptr);

    (void)in_sizes; (void)n_in; (void)out_size;
}

// round 15
// speedup vs baseline: 1.0306x; 1.0018x over previous
#include <cuda_runtime.h>
#include <cuda_fp16.h>
#include <cstdint>

// ---------------- problem constants ----------------
#define BB   2
#define SS   4096
#define DD   2048
#define HH   16
#define HD   128
#define CHUNK 64
#define NC   64
#define MROWS 8192
#define NBH  32
#define QSCALE 0.08838834764831845f
#define WSZ  (DD * DD)

// ---------------- scratch (device globals) ----------------
__device__ __align__(256) __half g_x1[(size_t)MROWS * DD];
__device__ __align__(256) __half g_w1[(size_t)4 * WSZ];
__device__ __align__(256) __half g_q1[(size_t)MROWS * DD];
__device__ __align__(256) __half g_k1[(size_t)MROWS * DD];
__device__ __align__(256) __half g_v1[(size_t)MROWS * DD];
__device__ __align__(256) __half g_o1[(size_t)MROWS * DD];
__device__ __align__(256) __half g_S1[(size_t)NBH * NC * HD * HD];

// ---------------- helpers ----------------
__device__ __forceinline__ uint32_t smem_u32(const void* p) {
    return (uint32_t)__cvta_generic_to_shared(p);
}
__device__ __forceinline__ void cp16(uint32_t d, const void* s) {
    asm volatile("cp.async.cg.shared.global [%0], [%1], 16;\n" :: "r"(d), "l"(s));
}
__device__ __forceinline__ void ldsm4(uint32_t* r, uint32_t a) {
    asm volatile("ldmatrix.sync.aligned.m8n8.x4.shared.b16 {%0,%1,%2,%3}, [%4];\n"
                 : "=r"(r[0]), "=r"(r[1]), "=r"(r[2]), "=r"(r[3]) : "r"(a));
}
__device__ __forceinline__ void ldsm4t(uint32_t* r, uint32_t a) {
    asm volatile("ldmatrix.sync.aligned.m8n8.x4.trans.shared.b16 {%0,%1,%2,%3}, [%4];\n"
                 : "=r"(r[0]), "=r"(r[1]), "=r"(r[2]), "=r"(r[3]) : "r"(a));
}
__device__ __forceinline__ void mma_f16(float* c, const uint32_t* a, const uint32_t* b) {
    asm volatile("mma.sync.aligned.m16n8k16.row.col.f32.f16.f16.f32 "
                 "{%0,%1,%2,%3}, {%4,%5,%6,%7}, {%8,%9}, {%0,%1,%2,%3};\n"
                 : "+f"(c[0]), "+f"(c[1]), "+f"(c[2]), "+f"(c[3])
                 : "r"(a[0]), "r"(a[1]), "r"(a[2]), "r"(a[3]), "r"(b[0]), "r"(b[1]));
}
__device__ __forceinline__ uint32_t pk2h(float a, float b) {
    __half2 t = __floats2half2_rn(a, b);
    return *(uint32_t*)&t;
}
__device__ __forceinline__ void split2h(float a, float b, uint32_t& H, uint32_t& L) {
    float ha = __half2float(__float2half_rn(a));
    float hb = __half2float(__float2half_rn(b));
    H = pk2h(a, b);
    L = pk2h(a - ha, b - hb);
}

// ---------------- fp32 -> fp16 convert (x + 4 weights, one launch) ----------------
// grid (WSZ/1024, 8): y 0..3 -> W matrices, y 4..7 -> quarters of x
__global__ __launch_bounds__(256) void cvt_all(
        const float* __restrict__ x,
        const float* __restrict__ w0, const float* __restrict__ w1f,
        const float* __restrict__ w2f, const float* __restrict__ w3f,
        __half* __restrict__ px, __half* __restrict__ pw) {
    const int y = blockIdx.y;
    size_t i = (size_t)blockIdx.x * 256 + threadIdx.x;
    const float* src;
    uint2* dst;
    if (y < 4) {
        src = (y == 0) ? w0 : (y == 1) ? w1f : (y == 2) ? w2f : w3f;
        dst = (uint2*)(pw + (size_t)y * WSZ);
    } else {
        const size_t qoff = (size_t)(y - 4) * (MROWS * (size_t)DD / 4);
        src = x + qoff;
        dst = (uint2*)(px + qoff);
    }
    float4 v = ((const float4*)src)[i];
    uint2 H;
    H.x = pk2h(v.x, v.y);
    H.y = pk2h(v.z, v.w);
    dst[i] = H;
}

// ================= fp16 single-pass GEMM: C = alpha*A1 B1^T, CTA 128x128, occ 2 =====
// R12-proven loop: 2-stage cp.async, K-step 64, issue->wait->sync->compute->sync.
// Stage 32KB: A1 @0, B1 @16384.
#define KIT 32
#define STG_B 32768
#define GEMM_SMEM (2 * STG_B)   // 65536 -> 2 CTAs per SM

__device__ __forceinline__ void issue_stage(uint32_t sbase,
        const __half* __restrict__ A1, const __half* __restrict__ B1,
        int k0, int tid) {
    #pragma unroll
    for (int i = 0; i < 4; i++) {             // A1: 128 rows x 8 chunks
        int idx = tid + i * 256;              // 0..1023
        int row = idx >> 3, c = idx & 7;
        const __half* src = A1 + (size_t)row * DD + k0 + c * 8;
        cp16(sbase + row * 128 + (((uint32_t)c ^ (row & 7)) << 4), src);
    }
    #pragma unroll
    for (int i = 0; i < 4; i++) {             // B1: 128 rows x 8 chunks
        int idx = tid + i * 256;
        int row = idx >> 3, c = idx & 7;
        const __half* src = B1 + (size_t)row * DD + k0 + c * 8;
        cp16(sbase + 16384 + row * 128 + (((uint32_t)c ^ (row & 7)) << 4), src);
    }
    asm volatile("cp.async.commit_group;\n" ::: "memory");
}

__device__ __forceinline__ void stage_compute(uint32_t sbase, int lane,
                                              int wm0, int wn0, float acc[4][4][4]) {
    const int arow = (lane & 7) + ((lane >> 3) & 1) * 8;
    const int asel = lane >> 4;
    const int brow = (lane & 7) + ((lane >> 4) << 3);
    const int bsel = (lane >> 3) & 1;
    #pragma unroll
    for (int ks = 0; ks < 4; ks++) {
        uint32_t a1[4][4];
        #pragma unroll
        for (int mf = 0; mf < 4; mf++) {
            int row = wm0 + mf * 16 + arow;
            int c = ks * 2 + asel;
            ldsm4(a1[mf], sbase + row * 128 + (((uint32_t)c ^ (row & 7)) << 4));
        }
        uint32_t b1[2][4];
        #pragma unroll
        for (int nq = 0; nq < 2; nq++) {
            int row = wn0 + nq * 16 + brow;
            int c = ks * 2 + bsel;
            ldsm4(b1[nq], sbase + 16384 + row * 128 + (((uint32_t)c ^ (row & 7)) << 4));
        }
        #pragma unroll
        for (int mf = 0; mf < 4; mf++)
            #pragma unroll
            for (int nf = 0; nf < 4; nf++) {
                const uint32_t* b = &b1[nf >> 1][(nf & 1) * 2];
                mma_f16(acc[mf][nf], a1[mf], b);
            }
    }
}

// If Cf != null: fp32 output (grid.x = 16). Else fused QKV (grid.x = 48):
// proj 0 -> Q1*QSCALE ; proj 1 -> K1 ; proj 2 -> V1 (all single fp16 planes).
__global__ __launch_bounds__(256, 2) void gemm_mma(
        const __half* __restrict__ A1, const __half* __restrict__ B1,
        float* __restrict__ Cf,
        uint32_t* __restrict__ Q1, uint32_t* __restrict__ K1,
        uint32_t* __restrict__ V1) {
    extern __shared__ char smc[];
    const uint32_t sb = smem_u32(smc);
    const int tid = threadIdx.x, lane = tid & 31, w = tid >> 5;
    const int bm0 = blockIdx.y * 128;
    const int bnG = blockIdx.x * 128;
    const int wm0 = (w >> 2) * 64, wn0 = (w & 3) * 32;
    const __half* At1 = A1 + (size_t)bm0 * DD;
    const __half* Bt1 = B1 + (size_t)bnG * DD;

    float acc[4][4][4];
    #pragma unroll
    for (int a = 0; a < 4; a++)
        #pragma unroll
        for (int b = 0; b < 4; b++)
            #pragma unroll
            for (int c = 0; c < 4; c++) acc[a][b][c] = 0.f;

    issue_stage(sb, At1, Bt1, 0, tid);

    for (int it = 0; it < KIT; ++it) {
        if (it + 1 < KIT) {
            issue_stage(sb + ((it + 1) & 1) * STG_B, At1, Bt1, (it + 1) * 64, tid);
            asm volatile("cp.async.wait_group 1;\n" ::: "memory");
        } else {
            asm volatile("cp.async.wait_group 0;\n" ::: "memory");
        }
        __syncthreads();
        stage_compute(sb + (it & 1) * STG_B, lane, wm0, wn0, acc);
        __syncthreads();
    }

    const int proj = (Cf == nullptr) ? (bnG >> 11) : 3;
    const int ncol0 = bnG & 2047;
    const float alpha = (proj == 0) ? QSCALE : 1.f;

    const int r0 = lane >> 2, c0 = lane & 3;
    #pragma unroll
    for (int mf = 0; mf < 4; mf++)
        #pragma unroll
        for (int nf = 0; nf < 4; nf++) {
            int row = bm0 + wm0 + mf * 16 + r0;
            int col = ncol0 + wn0 + nf * 8 + c0 * 2;
            float v0 = alpha * acc[mf][nf][0], v1 = alpha * acc[mf][nf][1];
            float v2 = alpha * acc[mf][nf][2], v3 = alpha * acc[mf][nf][3];
            if (Cf) {
                *(float2*)(Cf + (size_t)row * DD + col) = make_float2(v0, v1);
                *(float2*)(Cf + (size_t)(row + 8) * DD + col) = make_float2(v2, v3);
            } else {
                size_t pA = (size_t)row * (DD / 2) + (col >> 1);
                size_t pB = (size_t)(row + 8) * (DD / 2) + (col >> 1);
                uint32_t* Cp = (proj == 0) ? Q1 : (proj == 1) ? K1 : V1;
                Cp[pA] = pk2h(v0, v1);
                Cp[pB] = pk2h(v2, v3);
            }
        }
}

// ================= kvscan: fused KV outer-product + exclusive chunk scan ============
// Grid 128: blk = bh*4 + quad; quad -> (dh, eh) quadrant of the 128x128 state.
// Each CTA streams its bh's 64 chunks, keeps the running fp32 state for its
// 64x64 quadrant in registers, writes the EXCLUSIVE prefix as fp16 S per chunk,
// then mma-accumulates the chunk's K^T V. No KV intermediate in gmem.
#define KS_SMEM 32768   // 2 buffers x (K-half 8KB + V-half 8KB)
__global__ __launch_bounds__(256) void kvscan_mma(
        const __half* __restrict__ K1g, const __half* __restrict__ V1g,
        uint32_t* __restrict__ Sg) {
    extern __shared__ char smc[];
    const uint32_t sb = smem_u32(smc);
    const int tid = threadIdx.x, lane = tid & 31, w = tid >> 5;
    const int blk = blockIdx.x;                 // 0..127
    const int bh = blk >> 2, quad = blk & 3;
    const int dh = quad >> 1, eh = quad & 1;
    const int b = bh / HH, h = bh % HH;
    const int d0 = dh * 64, e0 = eh * 64;

    auto issue_ch = [&](int buf, int ch) {
        size_t grow = (size_t)(b * SS + ch * CHUNK);
        #pragma unroll
        for (int i = 0; i < 4; i++) {
            int idx = tid + i * 256;           // 0..1023
            int t2 = idx >> 9, rem = idx & 511;
            int row = rem >> 3, c = rem & 7;   // row = s 0..63, c = 16B chunk 0..7
            const __half* src = (t2 ? V1g : K1g)
                + (grow + row) * DD + h * HD + (t2 ? e0 : d0) + c * 8;
            cp16(sb + buf * 16384 + t2 * 8192 + row * 128
                 + (((uint32_t)c ^ (row & 7)) << 4), src);
        }
        asm volatile("cp.async.commit_group;\n" ::: "memory");
    };

    issue_ch(0, 0);

    // warp tile: 32(d) x 16(e); 8 warps cover 64x64
    const int wd = (w >> 2) * 32, we = (w & 3) * 16;
    const int j = lane & 7, g1 = (lane >> 3) & 1, g2 = lane >> 4;
    const int r0 = lane >> 2, c0 = (lane & 3) * 2;

    float run[2][2][4];
    #pragma unroll
    for (int mf = 0; mf < 2; mf++)
        #pragma unroll
        for (int nf = 0; nf < 2; nf++)
            #pragma unroll
            for (int e = 0; e < 4; e++) run[mf][nf][e] = 0.f;

    for (int ch = 0; ch < NC; ch++) {
        if (ch + 1 < NC) {
            issue_ch((ch + 1) & 1, ch + 1);
            asm volatile("cp.async.wait_group 1;\n" ::: "memory");
        } else {
            asm volatile("cp.async.wait_group 0;\n" ::: "memory");
        }
        __syncthreads();

        // write exclusive prefix (state BEFORE this chunk) as fp16 S
        uint32_t* out = Sg + (size_t)(bh * NC + ch) * (HD * HD / 2);
        #pragma unroll
        for (int mf = 0; mf < 2; mf++)
            #pragma unroll
            for (int nf = 0; nf < 2; nf++) {
                int d = d0 + wd + mf * 16 + r0;
                int e = e0 + we + nf * 8 + c0;
                out[(size_t)d * (HD / 2) + (e >> 1)] = pk2h(run[mf][nf][0], run[mf][nf][1]);
                out[(size_t)(d + 8) * (HD / 2) + (e >> 1)] = pk2h(run[mf][nf][2], run[mf][nf][3]);
            }

        // accumulate this chunk's K^T V into the running state
        const uint32_t sbk = sb + (ch & 1) * 16384;
        #pragma unroll
        for (int kb = 0; kb < 4; kb++) {
            uint32_t a1[2][4];
            #pragma unroll
            for (int mf = 0; mf < 2; mf++) {
                int row = kb * 16 + g2 * 8 + j;
                int c = (wd >> 3) + mf * 2 + g1;
                ldsm4t(a1[mf], sbk + row * 128 + (((uint32_t)c ^ (row & 7)) << 4));
            }
            uint32_t v1[4];
            {
                int row = kb * 16 + g1 * 8 + j;
                int c = (we >> 3) + g2;
                ldsm4t(v1, sbk + 8192 + row * 128 + (((uint32_t)c ^ (row & 7)) << 4));
            }
            #pragma unroll
            for (int mf = 0; mf < 2; mf++)
                #pragma unroll
                for (int nf = 0; nf < 2; nf++)
                    mma_f16(run[mf][nf], a1[mf], &v1[nf * 2]);
        }
        __syncthreads();
    }
}

// ================= attn: o = tril(q k^T) v + q S =================
#define ATTN_SMEM 81920
#define AQ1 0
#define AK1 16384
#define AV1 32768
#define AS1 49152

__global__ __launch_bounds__(256, 2) void attn_mma(
        const __half* __restrict__ Q1g, const __half* __restrict__ K1g,
        const __half* __restrict__ V1g, const __half* __restrict__ S1g,
        uint32_t* __restrict__ O1) {
    extern __shared__ char smc[];
    const uint32_t sb = smem_u32(smc);
    const int tid = threadIdx.x, lane = tid & 31, w = tid >> 5;
    const int blk = blockIdx.x;
    const int bh = blk / NC, cch = blk % NC;
    const int b = bh / HH, h = bh % HH;
    const size_t grow = (size_t)(b * SS + cch * CHUNK);

    const __half* tiles[3] = {Q1g, K1g, V1g};
    #pragma unroll
    for (int i = 0; i < 12; i++) {
        int t3 = i >> 2;
        int idx = tid + (i & 3) * 256;      // 0..1023
        int row = idx >> 4, c = idx & 15;
        const __half* src = tiles[t3] + (grow + row) * DD + h * HD + c * 8;
        cp16(sb + t3 * 16384 + row * 256 + (((uint32_t)c ^ (row & 7)) << 4), src);
    }
    const size_t sgb = (size_t)blk * (HD * HD);
    #pragma unroll
    for (int i = 0; i < 8; i++) {
        int idx = tid + i * 256;            // 0..2047
        int row = idx >> 4, c = idx & 15;
        const __half* src = S1g + sgb + (size_t)row * HD + c * 8;
        cp16(sb + AS1 + row * 256 + (((uint32_t)c ^ (row & 7)) << 4), src);
    }
    asm volatile("cp.async.commit_group;\ncp.async.wait_group 0;\n" ::: "memory");
    __syncthreads();

    const int mrow = (w >> 1) * 16, nh = w & 1;
    const int arow = (lane & 7) + ((lane >> 3) & 1) * 8;
    const int asel = lane >> 4;
    const int brow = (lane & 7) + ((lane >> 4) << 3);
    const int bsel = (lane >> 3) & 1;
    const int j = lane & 7, g1 = (lane >> 3) & 1, g2 = lane >> 4;

    // ---- qk^T ----
    float qk[8][4];
    #pragma unroll
    for (int n = 0; n < 8; n++)
        #pragma unroll
        for (int e = 0; e < 4; e++) qk[n][e] = 0.f;

    #pragma unroll
    for (int kb = 0; kb < 8; kb++) {
        uint32_t q1[4];
        {
            int row = mrow + arow;
            int c = kb * 2 + asel;
            ldsm4(q1, sb + AQ1 + row * 256 + (((uint32_t)c ^ (row & 7)) << 4));
        }
        uint32_t k1[4][4];
        #pragma unroll
        for (int nq = 0; nq < 4; nq++) {
            int row = nq * 16 + brow;
            int c = kb * 2 + bsel;
            ldsm4(k1[nq], sb + AK1 + row * 256 + (((uint32_t)c ^ (row & 7)) << 4));
        }
        #pragma unroll
        for (int nf = 0; nf < 8; nf++) {
            const uint32_t* bb = &k1[nf >> 1][(nf & 1) * 2];
            mma_f16(qk[nf], q1, bb);
        }
    }
    // ---- causal mask ----
    const int r0 = lane >> 2, c0 = (lane & 3) * 2;
    #pragma unroll
    for (int nf = 0; nf < 8; nf++)
        #pragma unroll
        for (int e = 0; e < 4; e++) {
            int rloc = mrow + r0 + ((e >= 2) ? 8 : 0);
            int scol = nf * 8 + c0 + (e & 1);
            if (scol > rloc) qk[nf][e] = 0.f;
        }

    float o[8][4];
    #pragma unroll
    for (int n = 0; n < 8; n++)
        #pragma unroll
        for (int e = 0; e < 4; e++) o[n][e] = 0.f;

    // ---- intra: o += attn @ V  (2-pass register split of attn) ----
    #pragma unroll
    for (int kb2 = 0; kb2 < 4; kb2++) {
        uint32_t Ah[4], Al[4];
        split2h(qk[2 * kb2][0],     qk[2 * kb2][1],     Ah[0], Al[0]);
        split2h(qk[2 * kb2][2],     qk[2 * kb2][3],     Ah[1], Al[1]);
        split2h(qk[2 * kb2 + 1][0], qk[2 * kb2 + 1][1], Ah[2], Al[2]);
        split2h(qk[2 * kb2 + 1][2], qk[2 * kb2 + 1][3], Ah[3], Al[3]);
        uint32_t v1[4][4];
        #pragma unroll
        for (int nf2 = 0; nf2 < 4; nf2++) {
            int row = kb2 * 16 + g1 * 8 + j;
            int c = nh * 8 + nf2 * 2 + g2;
            ldsm4t(v1[nf2], sb + AV1 + row * 256 + (((uint32_t)c ^ (row & 7)) << 4));
        }
        #pragma unroll
        for (int nf = 0; nf < 8; nf++) {
            const uint32_t* bb = &v1[nf >> 1][(nf & 1) * 2];
            mma_f16(o[nf], Ah, bb);
            mma_f16(o[nf], Al, bb);
        }
    }
    // ---- inter: o += q @ S ----
    #pragma unroll
    for (int kb = 0; kb < 8; kb++) {
        uint32_t q1[4];
        {
            int row = mrow + arow;
            int c = kb * 2 + asel;
            ldsm4(q1, sb + AQ1 + row * 256 + (((uint32_t)c ^ (row & 7)) << 4));
        }
        uint32_t s1[4][4];
        #pragma unroll
        for (int nf2 = 0; nf2 < 4; nf2++) {
            int row = kb * 16 + g1 * 8 + j;
            int c = nh * 8 + nf2 * 2 + g2;
            ldsm4t(s1[nf2], sb + AS1 + row * 256 + (((uint32_t)c ^ (row & 7)) << 4));
        }
        #pragma unroll
        for (int nf = 0; nf < 8; nf++) {
            const uint32_t* bb = &s1[nf >> 1][(nf & 1) * 2];
            mma_f16(o[nf], q1, bb);
        }
    }
    // ---- epilogue: write o as single fp16 plane ----
    #pragma unroll
    for (int nf = 0; nf < 8; nf++) {
        int col = h * HD + nh * 64 + nf * 8 + c0;
        size_t pA = (grow + mrow + r0) * (DD / 2) + (col >> 1);
        size_t pB = (grow + mrow + r0 + 8) * (DD / 2) + (col >> 1);
        O1[pA] = pk2h(o[nf][0], o[nf][1]);
        O1[pB] = pk2h(o[nf][2], o[nf][3]);
    }
}

// ---------------------------------------------------------------------------
extern "C" void kernel_launch(void* const* d_in, const int* in_sizes, int n_in,
                              void* d_out, int out_size) {
    const float* x  = (const float*)d_in[0];
    const float* Wq = (const float*)d_in[1];
    const float* Wk = (const float*)d_in[2];
    const float* Wv = (const float*)d_in[3];
    const float* Wo = (const float*)d_in[4];
    float* out = (float*)d_out;

    __half *px1, *pw1, *pq1, *pk1, *pv1, *po1, *pS1;
    cudaGetSymbolAddress((void**)&px1, g_x1);
    cudaGetSymbolAddress((void**)&pw1, g_w1);
    cudaGetSymbolAddress((void**)&pq1, g_q1);
    cudaGetSymbolAddress((void**)&pk1, g_k1);
    cudaGetSymbolAddress((void**)&pv1, g_v1);
    cudaGetSymbolAddress((void**)&po1, g_o1);
    cudaGetSymbolAddress((void**)&pS1, g_S1);

    cudaFuncSetAttribute(gemm_mma,   cudaFuncAttributeMaxDynamicSharedMemorySize, GEMM_SMEM);
    cudaFuncSetAttribute(kvscan_mma, cudaFuncAttributeMaxDynamicSharedMemorySize, KS_SMEM);
    cudaFuncSetAttribute(attn_mma,   cudaFuncAttributeMaxDynamicSharedMemorySize, ATTN_SMEM);

    // converts: x and all W -> single fp16 planes, one launch
    dim3 cgrid(WSZ / 1024, 8);
    cvt_all<<<cgrid, 256>>>(x, Wq, Wk, Wv, Wo, px1, pw1);

    // fused Q,K,V projections (B = [Wq; Wk; Wv] contiguous in g_w1)
    dim3 qkvgrid(3 * DD / 128, MROWS / 128);   // (48, 64)
    gemm_mma<<<qkvgrid, 256, GEMM_SMEM>>>(px1, pw1, nullptr,
                                          (uint32_t*)pq1, (uint32_t*)pk1,
                                          (uint32_t*)pv1);

    // fused KV outer-product + exclusive scan -> S (fp16)
    kvscan_mma<<<NBH * 4, 256, KS_SMEM>>>(pk1, pv1, (uint32_t*)pS1);

    attn_mma<<<NBH * NC, 256, ATTN_SMEM>>>(pq1, pk1, pv1, pS1, (uint32_t*)po1);

    // output projection (fp32 out)
    dim3 ogrid(DD / 128, MROWS / 128);         // (16, 64)
    gemm_mma<<<ogrid, 256, GEMM_SMEM>>>(po1, pw1 + 3 * (size_t)WSZ, out,
                                        nullptr, nullptr, nullptr);

    (void)in_sizes; (void)n_in; (void)out_size;
}